// round 11
// baseline (speedup 1.0000x reference)
#include <cuda_runtime.h>
#include <math.h>

#define NPTS    16384               // 8 * 2048 points per cloud
#define DIM     48                  // cells per axis
#define DIM2    (DIM * DIM)
#define NCELLS  (DIM * DIM * DIM)   // 110592
#define ORG     (-6.0f)
#define H       0.25f
#define INVH    4.0f
#define SCAN_T  1024
#define CPT     (NCELLS / SCAN_T)   // 108 cells per scan thread (27 int4)
#define SPAD    (NCELLS + 4)        // padded row: keeps row 1 16B-aligned
#define KMAX    4                   // shell cap; unresolved -> brute phase

__device__ float4 g_sorted[2][NPTS];        // cell-sorted points
__device__ int    g_count [2][NCELLS];
__device__ int    g_start [2][SPAD];        // [NCELLS] = sentinel (NPTS)
__device__ int    g_cursor[2][NCELLS];
__device__ int    g_cellid[2][NPTS];
__device__ int    g_occ[2 * NPTS];          // occupied cells: cell | (cloud<<17)
__device__ int    g_nocc;
__device__ int    g_pending[2 * NPTS];      // unresolved query ids
__device__ int    g_pcount;

__device__ __forceinline__ int cell_coord(float v) {
    int c = (int)floorf((v - ORG) * INVH);
    return min(DIM - 1, max(0, c));
}

// ---------------------------------------------------------------- K0: zero
__global__ void zero_kernel(float* __restrict__ out) {
    int i = blockIdx.x * blockDim.x + threadIdx.x;
    if (i == 0) { out[0] = 0.0f; g_pcount = 0; g_nocc = 0; }
    if (i < NCELLS / 4) {
        reinterpret_cast<int4*>(g_count[0])[i] = make_int4(0, 0, 0, 0);
        reinterpret_cast<int4*>(g_count[1])[i] = make_int4(0, 0, 0, 0);
    }
}

// ----------------------------------- K1: histogram + occupied-cell compact
__global__ void hist_kernel(const float* __restrict__ pc1,
                            const float* __restrict__ pc2) {
    int i = blockIdx.x * blockDim.x + threadIdx.x;
    if (i >= 2 * NPTS) return;
    int c = (i >= NPTS) ? 1 : 0;
    int j = i - c * NPTS;
    const float* pc = c ? pc2 : pc1;
    float x = pc[3 * j + 0], y = pc[3 * j + 1], z = pc[3 * j + 2];
    int cell = (cell_coord(z) * DIM + cell_coord(y)) * DIM + cell_coord(x);
    g_cellid[c][j] = cell;
    int old = atomicAdd(&g_count[c][cell], 1);
    if (old == 0) {
        int idx = atomicAdd(&g_nocc, 1);
        g_occ[idx] = cell | (c << 17);
    }
}

// ------------------------------------------------- K2: scan (1 block/cloud)
__global__ void __launch_bounds__(SCAN_T)
scan_kernel() {
    const int c = blockIdx.x;
    const int t = threadIdx.x;
    __shared__ int sm[SCAN_T];

    const int4* __restrict__ cnt4 =
        reinterpret_cast<const int4*>(g_count[c]) + t * (CPT / 4);

    int4 v[CPT / 4];
    int local = 0;
    #pragma unroll
    for (int i = 0; i < CPT / 4; ++i) {
        v[i] = cnt4[i];
        local += v[i].x + v[i].y + v[i].z + v[i].w;
    }
    sm[t] = local;
    __syncthreads();

    #pragma unroll
    for (int off = 1; off < SCAN_T; off <<= 1) {
        int u = (t >= off) ? sm[t - off] : 0;
        __syncthreads();
        sm[t] += u;
        __syncthreads();
    }

    int run = sm[t] - local;
    int4* __restrict__ st4 = reinterpret_cast<int4*>(g_start[c])  + t * (CPT / 4);
    int4* __restrict__ cu4 = reinterpret_cast<int4*>(g_cursor[c]) + t * (CPT / 4);
    #pragma unroll
    for (int i = 0; i < CPT / 4; ++i) {
        int4 s;
        s.x = run;            run += v[i].x;
        s.y = run;            run += v[i].y;
        s.z = run;            run += v[i].z;
        s.w = run;            run += v[i].w;
        st4[i] = s;
        cu4[i] = s;
    }
    if (t == SCAN_T - 1) g_start[c][NCELLS] = NPTS;
}

// -------------------------------------------------------------- K3: scatter
__global__ void scatter_kernel(const float* __restrict__ pc1,
                               const float* __restrict__ pc2) {
    int i = blockIdx.x * blockDim.x + threadIdx.x;
    if (i >= 2 * NPTS) return;
    int c = (i >= NPTS) ? 1 : 0;
    int j = i - c * NPTS;
    const float* pc = c ? pc2 : pc1;
    float x = pc[3 * j + 0], y = pc[3 * j + 1], z = pc[3 * j + 2];
    int cell = g_cellid[c][j];
    int pos = atomicAdd(&g_cursor[c][cell], 1);
    g_sorted[c][pos] = make_float4(x, y, z, 0.0f);
}

// Stream candidates [s, e) in 32-wide chunks through SMEM; every candidate is
// evaluated against this lane's query. Warp-uniform s, e.
__device__ __forceinline__ void stream_span(float4* __restrict__ buf,
                                            const float4* __restrict__ tgt,
                                            int s, int e, int lane,
                                            float qx, float qy, float qz,
                                            float& best2) {
    for (int base = s; base < e; base += 32) {
        const int n = min(32, e - base);
        if (lane < n) buf[lane] = tgt[base + lane];   // coalesced
        __syncwarp();
        for (int i = 0; i < n; ++i) {
            const float4 b = buf[i];                  // LDS broadcast
            const float dx = qx - b.x;
            const float dy = qy - b.y;
            const float dz = qz - b.z;
            const float d2 = fmaf(dx, dx, fmaf(dy, dy, dz * dz));
            best2 = fminf(best2, d2);
        }
        __syncwarp();
    }
}

// --------- K4: cell-batched warp NN query (phase A)
// One warp per occupied query cell (grid-stride). Lanes = queries of that
// cell (chunked by 32). Box rows walked once per cell; candidates streamed
// 32-wide so each candidate serves all lane-queries simultaneously.
__global__ void __launch_bounds__(256)
query_kernel(float* __restrict__ out) {
    __shared__ float4 buf[8][32];
    const int lane  = threadIdx.x & 31;
    const int wslot = threadIdx.x >> 5;
    const int gwarp = (blockIdx.x * blockDim.x + threadIdx.x) >> 5;
    const int nwarp = (gridDim.x * blockDim.x) >> 5;
    const int total = g_nocc;

    float dsum = 0.0f;

    for (int ci = gwarp; ci < total; ci += nwarp) {
        const int ent  = g_occ[ci];
        const int dir  = ent >> 17;
        const int cell = ent & 0x1FFFF;
        const int tc   = dir ^ 1;

        const float4* __restrict__ tgt = g_sorted[tc];
        const int*    __restrict__ cst = g_start[tc];

        const int cx = cell % DIM;
        const int cy = (cell / DIM) % DIM;
        const int cz = cell / DIM2;

        const int qs = g_start[dir][cell];
        const int qe = g_start[dir][cell + 1];

        const int x0 = max(cx - 1, 0), x1 = min(cx + 1, DIM - 1);
        const int zb0 = max(cz - 1, 0), zb1 = min(cz + 1, DIM - 1);
        const int yb0 = max(cy - 1, 0), yb1 = min(cy + 1, DIM - 1);

        for (int qb = qs; qb < qe; qb += 32) {
            const int qn = qe - qb;                   // remaining queries
            const bool active = lane < qn;
            const float4 q = g_sorted[dir][qb + (active ? lane : 0)];

            // Per-query margin to own-cell faces (for the sharp bound).
            const float fx = q.x - (ORG + (float)cx * H);
            const float fy = q.y - (ORG + (float)cy * H);
            const float fz = q.z - (ORG + (float)cz * H);
            const float mfr = fmaxf(0.0f,
                fminf(fminf(fminf(fx, H - fx), fminf(fy, H - fy)),
                      fminf(fz, H - fz)));

            float best2 = 3.0e38f;

            // ---- Box(1): 9 contiguous row spans, candidates shared by all lanes.
            for (int z = zb0; z <= zb1; ++z)
                for (int y = yb0; y <= yb1; ++y) {
                    const int rb = z * DIM2 + y * DIM;
                    stream_span(buf[wslot], tgt,
                                cst[rb + x0], cst[rb + x1 + 1], lane,
                                q.x, q.y, q.z, best2);
                }

            float bound = H + mfr;
            bool resolved = best2 <= bound * bound;

            // ---- Shells (warp-uniform geometry), while any lane unresolved.
            int k = 1;
            while (k < KMAX &&
                   __any_sync(0xFFFFFFFFu, active && !resolved)) {
                ++k;
                const int z0 = max(cz - k, 0), z1 = min(cz + k, DIM - 1);
                const int y0 = max(cy - k, 0), y1 = min(cy + k, DIM - 1);
                const int xl = cx - k, xr = cx + k;
                const int xs = max(xl, 0), xe = min(xr, DIM - 1);
                for (int z = z0; z <= z1; ++z) {
                    const bool zface = (z - cz == -k) || (z - cz == k);
                    for (int y = y0; y <= y1; ++y) {
                        const int rb = z * DIM2 + y * DIM;
                        if (zface || (y - cy == -k) || (y - cy == k)) {
                            stream_span(buf[wslot], tgt,
                                        cst[rb + xs], cst[rb + xe + 1], lane,
                                        q.x, q.y, q.z, best2);
                        } else {
                            if (xl >= 0)
                                stream_span(buf[wslot], tgt,
                                            cst[rb + xl], cst[rb + xl + 1], lane,
                                            q.x, q.y, q.z, best2);
                            if (xr <= DIM - 1)
                                stream_span(buf[wslot], tgt,
                                            cst[rb + xr], cst[rb + xr + 1], lane,
                                            q.x, q.y, q.z, best2);
                        }
                    }
                }
                bound = (float)k * H + mfr;
                resolved = best2 <= bound * bound;
            }

            if (active) {
                if (resolved) {
                    dsum += sqrtf(fmaxf(best2, 0.0f));
                } else {
                    int idx = atomicAdd(&g_pcount, 1);
                    g_pending[idx] = (dir << 14) | (qb + lane);
                }
            }
        }
    }

    // Block reduction of dsum, one atomicAdd per block.
    __shared__ float warp_sums[8];
    float v = dsum;
    #pragma unroll
    for (int off = 16; off > 0; off >>= 1)
        v += __shfl_xor_sync(0xFFFFFFFFu, v, off);
    if (lane == 0) warp_sums[wslot] = v;
    __syncthreads();
    if (threadIdx.x < 32) {
        float s = (lane < 8) ? warp_sums[lane] : 0.0f;
        #pragma unroll
        for (int off = 4; off > 0; off >>= 1)
            s += __shfl_xor_sync(0xFFFFFFFFu, s, off);
        if (lane == 0 && s != 0.0f)
            atomicAdd(out, s * (1.0f / (float)NPTS));
    }
}

// ------------------- K5: brute-force for unresolved queries (phase B)
__global__ void __launch_bounds__(256)
brute_kernel(float* __restrict__ out) {
    const int gw   = (blockIdx.x * blockDim.x + threadIdx.x) >> 5;
    const int lane = threadIdx.x & 31;
    const int nw   = (gridDim.x * blockDim.x) >> 5;
    const int n    = g_pcount;

    for (int w = gw; w < n; w += nw) {
        const int gq  = g_pending[w];
        const int dir = gq >> 14;
        const int qi  = gq & (NPTS - 1);
        const float4 q = g_sorted[dir][qi];
        const float4* __restrict__ tgt = g_sorted[dir ^ 1];

        float best2 = 3.0e38f;
        for (int p = lane; p < NPTS; p += 32) {
            const float4 b = tgt[p];
            const float dx = q.x - b.x;
            const float dy = q.y - b.y;
            const float dz = q.z - b.z;
            const float d2 = fmaf(dx, dx, fmaf(dy, dy, dz * dz));
            best2 = fminf(best2, d2);
        }
        #pragma unroll
        for (int off = 16; off > 0; off >>= 1)
            best2 = fminf(best2, __shfl_xor_sync(0xFFFFFFFFu, best2, off));
        if (lane == 0)
            atomicAdd(out, sqrtf(fmaxf(best2, 0.0f)) * (1.0f / (float)NPTS));
    }
}

extern "C" void kernel_launch(void* const* d_in, const int* in_sizes, int n_in,
                              void* d_out, int out_size) {
    const float* pc1 = (const float*)d_in[0];
    const float* pc2 = (const float*)d_in[1];
    float* out = (float*)d_out;

    zero_kernel   <<<(NCELLS / 4 + 255) / 256, 256>>>(out);
    hist_kernel   <<<(2 * NPTS + 255) / 256, 256>>>(pc1, pc2);
    scan_kernel   <<<2, SCAN_T>>>();
    scatter_kernel<<<(2 * NPTS + 255) / 256, 256>>>(pc1, pc2);
    query_kernel  <<<512, 256>>>(out);
    brute_kernel  <<<64, 256>>>(out);
}

// round 12
// speedup vs baseline: 2.4235x; 2.4235x over previous
#include <cuda_runtime.h>
#include <math.h>

#define NPTS    16384               // 8 * 2048 points per cloud
#define DIM     32                  // cells per axis
#define DIM2    (DIM * DIM)
#define NCELLS  (DIM * DIM * DIM)   // 32768
#define ORG     (-5.0f)
#define H       0.3125f
#define INVH    3.2f
#define SCAN_T  1024
#define CPT     (NCELLS / SCAN_T)   // 32 cells per scan thread (8 int4)
#define SPAD    (NCELLS + 4)        // padded row: keeps row 1 16B-aligned

__device__ float4 g_sorted[2][NPTS];        // cell-sorted points
__device__ int    g_count [2][NCELLS];
__device__ int    g_start [2][SPAD];        // [NCELLS] = sentinel (NPTS)
__device__ int    g_cursor[2][NCELLS];
__device__ int    g_cellid[2][NPTS];
__device__ int    g_pending[2 * NPTS];      // unresolved query ids
__device__ int    g_pcount;

__device__ __forceinline__ int cell_coord(float v) {
    int c = (int)floorf((v - ORG) * INVH);
    return min(DIM - 1, max(0, c));
}

// ---------------------------------------------------------------- K0: zero
__global__ void zero_kernel(float* __restrict__ out) {
    int i = blockIdx.x * blockDim.x + threadIdx.x;
    if (i == 0) { out[0] = 0.0f; g_pcount = 0; }
    if (i < NCELLS / 4) {
        reinterpret_cast<int4*>(g_count[0])[i] = make_int4(0, 0, 0, 0);
        reinterpret_cast<int4*>(g_count[1])[i] = make_int4(0, 0, 0, 0);
    }
}

// ------------------------------------------------------------ K1: histogram
__global__ void hist_kernel(const float* __restrict__ pc1,
                            const float* __restrict__ pc2) {
    int i = blockIdx.x * blockDim.x + threadIdx.x;
    if (i >= 2 * NPTS) return;
    int c = (i >= NPTS) ? 1 : 0;
    int j = i - c * NPTS;
    const float* pc = c ? pc2 : pc1;
    float x = pc[3 * j + 0], y = pc[3 * j + 1], z = pc[3 * j + 2];
    int cell = (cell_coord(z) * DIM + cell_coord(y)) * DIM + cell_coord(x);
    g_cellid[c][j] = cell;
    atomicAdd(&g_count[c][cell], 1);
}

// ------------------------------------------------- K2: scan (1 block/cloud)
__global__ void __launch_bounds__(SCAN_T)
scan_kernel() {
    const int c = blockIdx.x;
    const int t = threadIdx.x;
    __shared__ int sm[SCAN_T];

    const int4* __restrict__ cnt4 =
        reinterpret_cast<const int4*>(g_count[c]) + t * (CPT / 4);

    int4 v[CPT / 4];
    int local = 0;
    #pragma unroll
    for (int i = 0; i < CPT / 4; ++i) {
        v[i] = cnt4[i];
        local += v[i].x + v[i].y + v[i].z + v[i].w;
    }
    sm[t] = local;
    __syncthreads();

    #pragma unroll
    for (int off = 1; off < SCAN_T; off <<= 1) {
        int u = (t >= off) ? sm[t - off] : 0;
        __syncthreads();
        sm[t] += u;
        __syncthreads();
    }

    int run = sm[t] - local;
    int4* __restrict__ st4 = reinterpret_cast<int4*>(g_start[c])  + t * (CPT / 4);
    int4* __restrict__ cu4 = reinterpret_cast<int4*>(g_cursor[c]) + t * (CPT / 4);
    #pragma unroll
    for (int i = 0; i < CPT / 4; ++i) {
        int4 s;
        s.x = run;            run += v[i].x;
        s.y = run;            run += v[i].y;
        s.z = run;            run += v[i].z;
        s.w = run;            run += v[i].w;
        st4[i] = s;
        cu4[i] = s;
    }
    if (t == SCAN_T - 1) g_start[c][NCELLS] = NPTS;
}

// -------------------------------------------------------------- K3: scatter
__global__ void scatter_kernel(const float* __restrict__ pc1,
                               const float* __restrict__ pc2) {
    int i = blockIdx.x * blockDim.x + threadIdx.x;
    if (i >= 2 * NPTS) return;
    int c = (i >= NPTS) ? 1 : 0;
    int j = i - c * NPTS;
    const float* pc = c ? pc2 : pc1;
    float x = pc[3 * j + 0], y = pc[3 * j + 1], z = pc[3 * j + 2];
    int cell = g_cellid[c][j];
    int pos = atomicAdd(&g_cursor[c][cell], 1);
    g_sorted[c][pos] = make_float4(x, y, z, 0.0f);
}

// Scan cells [c0, c1]; points split stride-4 over the quad.
__device__ __forceinline__ void scan_q4(const float4* __restrict__ tgt,
                                        const int* __restrict__ cst,
                                        int c0, int c1, int sub,
                                        float qx, float qy, float qz,
                                        float& best2) {
    const int s = cst[c0];
    const int e = cst[c1 + 1];
    for (int p = s + sub; p < e; p += 4) {
        const float4 b = tgt[p];
        const float dx = qx - b.x;
        const float dy = qy - b.y;
        const float dz = qz - b.z;
        const float d2 = fmaf(dx, dx, fmaf(dy, dy, dz * dz));
        best2 = fminf(best2, d2);
    }
}

// --------- K4: box(1)-only quad-cooperative NN (phase A). No shells.
// Resolved iff best distance <= H + margin-to-own-cell-face (any point
// outside box(1) is at least that far). Unresolved -> pending.
__global__ void __launch_bounds__(256)
query_kernel(float* __restrict__ out) {
    const int t    = blockIdx.x * blockDim.x + threadIdx.x;  // 0 .. 131071
    const int sub  = t & 3;
    const int gq   = t >> 2;            // 0 .. 32767
    const int dir  = gq >> 14;
    const int qi   = gq & (NPTS - 1);
    const int tc   = dir ^ 1;
    const unsigned qmask = 0xFu << (threadIdx.x & 28);

    const float4 q = g_sorted[dir][qi];
    const int cx = cell_coord(q.x);
    const int cy = cell_coord(q.y);
    const int cz = cell_coord(q.z);
    const float fx = q.x - (ORG + (float)cx * H);
    const float fy = q.y - (ORG + (float)cy * H);
    const float fz = q.z - (ORG + (float)cz * H);
    const float mfr = fmaxf(0.0f,
        fminf(fminf(fminf(fx, H - fx), fminf(fy, H - fy)),
              fminf(fz, H - fz)));

    const float4* __restrict__ tgt = g_sorted[tc];
    const int*    __restrict__ cst = g_start[tc];

    float best2 = 3.0e38f;

    const int x0 = max(cx - 1, 0), x1 = min(cx + 1, DIM - 1);
    const int z0 = max(cz - 1, 0), z1 = min(cz + 1, DIM - 1);
    const int y0 = max(cy - 1, 0), y1 = min(cy + 1, DIM - 1);
    for (int z = z0; z <= z1; ++z)
        for (int y = y0; y <= y1; ++y) {
            const int rb = z * DIM2 + y * DIM;
            scan_q4(tgt, cst, rb + x0, rb + x1, sub, q.x, q.y, q.z, best2);
        }

    best2 = fminf(best2, __shfl_xor_sync(qmask, best2, 1));
    best2 = fminf(best2, __shfl_xor_sync(qmask, best2, 2));

    const float bound = H + mfr;
    const bool resolved = best2 <= bound * bound;

    float d = 0.0f;
    if (sub == 0) {
        if (resolved) {
            d = sqrtf(fmaxf(best2, 0.0f));
        } else {
            int idx = atomicAdd(&g_pcount, 1);
            g_pending[idx] = gq;
        }
    }

    // Block reduction (256 threads = 8 warps), one atomicAdd per block.
    __shared__ float warp_sums[8];
    float v = d;
    #pragma unroll
    for (int off = 16; off > 0; off >>= 1)
        v += __shfl_xor_sync(0xFFFFFFFFu, v, off);
    const int lane = threadIdx.x & 31;
    const int wid  = threadIdx.x >> 5;
    if (lane == 0) warp_sums[wid] = v;
    __syncthreads();
    if (wid == 0) {
        float s = (lane < 8) ? warp_sums[lane] : 0.0f;
        #pragma unroll
        for (int off = 4; off > 0; off >>= 1)
            s += __shfl_xor_sync(0xFFFFFFFFu, s, off);
        if (lane == 0)
            atomicAdd(out, s * (1.0f / (float)NPTS));
    }
}

// ------------------- K5: warp-per-query brute force (phase B)
__global__ void __launch_bounds__(256)
brute_kernel(float* __restrict__ out) {
    const int gw   = (blockIdx.x * blockDim.x + threadIdx.x) >> 5;
    const int lane = threadIdx.x & 31;
    const int nw   = (gridDim.x * blockDim.x) >> 5;
    const int n    = g_pcount;

    for (int w = gw; w < n; w += nw) {
        const int gq  = g_pending[w];
        const int dir = gq >> 14;
        const int qi  = gq & (NPTS - 1);
        const float4 q = g_sorted[dir][qi];
        const float4* __restrict__ tgt = g_sorted[dir ^ 1];

        float best2 = 3.0e38f;
        for (int p = lane; p < NPTS; p += 32) {
            const float4 b = tgt[p];
            const float dx = q.x - b.x;
            const float dy = q.y - b.y;
            const float dz = q.z - b.z;
            const float d2 = fmaf(dx, dx, fmaf(dy, dy, dz * dz));
            best2 = fminf(best2, d2);
        }
        #pragma unroll
        for (int off = 16; off > 0; off >>= 1)
            best2 = fminf(best2, __shfl_xor_sync(0xFFFFFFFFu, best2, off));
        if (lane == 0)
            atomicAdd(out, sqrtf(fmaxf(best2, 0.0f)) * (1.0f / (float)NPTS));
    }
}

extern "C" void kernel_launch(void* const* d_in, const int* in_sizes, int n_in,
                              void* d_out, int out_size) {
    const float* pc1 = (const float*)d_in[0];
    const float* pc2 = (const float*)d_in[1];
    float* out = (float*)d_out;

    zero_kernel   <<<(NCELLS / 4 + 255) / 256, 256>>>(out);
    hist_kernel   <<<(2 * NPTS + 255) / 256, 256>>>(pc1, pc2);
    scan_kernel   <<<2, SCAN_T>>>();
    scatter_kernel<<<(2 * NPTS + 255) / 256, 256>>>(pc1, pc2);
    query_kernel  <<<(2 * NPTS * 4) / 256, 256>>>(out);
    brute_kernel  <<<148, 256>>>(out);
}